// round 5
// baseline (speedup 1.0000x reference)
#include <cuda_runtime.h>
#include <cstdint>

#define U_N   100000
#define I_N   50000
#define R_N   5
#define E_N   100000
#define K_N   4
#define D_N   16
#define RD_N  64
#define OUT_N 64
#define KF_N  2

// rproj blocks: 64 edges each
#define RP_BLOCKS ((E_N + 63) / 64)          // 1563
#define P1_BLOCKS (E_N / 8)                  // 12500

// ---------------- device scratch ----------------
__device__ float g_norm_u[U_N];
__device__ float g_norm_i[I_N];
__device__ float g_ead[R_N * E_N];
__device__ float g_m[(size_t)R_N * E_N * 32];        // per edge: [0..15]=Rf_fwd, [16..31]=Rf_rev
__device__ float g_ufeat[U_N * D_N];
__device__ float g_ifeat[I_N * D_N];
__device__ float g_invn_u[R_N * U_N];
__device__ float g_invn_i[R_N * I_N];
__device__ float g_P_u[(size_t)R_N * U_N * D_N];     // user_h @ node_w_fwd
__device__ float g_P_i[(size_t)R_N * I_N * D_N];     // item_h @ node_w_rev

// ---------------- helpers ----------------
__device__ __forceinline__ float red16(float v) {
    v += __shfl_xor_sync(0xffffffffu, v, 1);
    v += __shfl_xor_sync(0xffffffffu, v, 2);
    v += __shfl_xor_sync(0xffffffffu, v, 4);
    v += __shfl_xor_sync(0xffffffffu, v, 8);
    return v;
}
__device__ __forceinline__ float red32(float v) {
    v = red16(v);
    v += __shfl_xor_sync(0xffffffffu, v, 16);
    return v;
}
__device__ __forceinline__ void red_v4(float* addr, float4 v) {
    asm volatile("red.global.add.v4.f32 [%0], {%1, %2, %3, %4};"
                 :: "l"(addr), "f"(v.x), "f"(v.y), "f"(v.z), "f"(v.w)
                 : "memory");
}

// ---------------- kernel A: invnorm + node projection + accumulator zeroing ----------------
// grid: (ceil(U/256), R, 2)  z=0 users, z=1 items.
__global__ __launch_bounds__(256) void precompute_kernel(
    const float* __restrict__ user_h, const float* __restrict__ item_h,
    const float* __restrict__ node_w_fwd, const float* __restrict__ node_w_rev)
{
    __shared__ float sw[256];
    const int r = blockIdx.y;
    const bool isU = (blockIdx.z == 0);
    const float* W = isU ? node_w_fwd : node_w_rev;
    if (threadIdx.x < 256) sw[threadIdx.x] = W[r * 256 + threadIdx.x];
    __syncthreads();

    const int N = isU ? U_N : I_N;
    const int n = blockIdx.x * 256 + threadIdx.x;
    if (n >= N) return;

    // fold in the zeroing of the global accumulators (r==0 blocks only)
    if (r == 0) {
        float4 z = {0.f, 0.f, 0.f, 0.f};
        if (isU) {
            g_norm_u[n] = 0.f;
            float4* f = (float4*)(g_ufeat + n * 16);
            f[0] = z; f[1] = z; f[2] = z; f[3] = z;
        } else {
            g_norm_i[n] = 0.f;
            float4* f = (float4*)(g_ifeat + n * 16);
            f[0] = z; f[1] = z; f[2] = z; f[3] = z;
        }
    }

    const float* h = (isU ? user_h : item_h) + ((size_t)r * N + n) * 16;
    float xs[16];
    const float4* h4 = (const float4*)h;
    float4 x0 = h4[0], x1 = h4[1], x2 = h4[2], x3 = h4[3];
    xs[0]=x0.x; xs[1]=x0.y; xs[2]=x0.z; xs[3]=x0.w;
    xs[4]=x1.x; xs[5]=x1.y; xs[6]=x1.z; xs[7]=x1.w;
    xs[8]=x2.x; xs[9]=x2.y; xs[10]=x2.z; xs[11]=x2.w;
    xs[12]=x3.x; xs[13]=x3.y; xs[14]=x3.z; xs[15]=x3.w;

    float ss = 0.f;
#pragma unroll
    for (int j = 0; j < 16; j++) ss = fmaf(xs[j], xs[j], ss);
    float invn = rsqrtf(ss);
    if (isU) g_invn_u[(size_t)r * U_N + n] = invn;
    else     g_invn_i[(size_t)r * I_N + n] = invn;

    float4 a0 = {0,0,0,0}, a1 = {0,0,0,0}, a2 = {0,0,0,0}, a3 = {0,0,0,0};
    const float4* sw4 = (const float4*)sw;
#pragma unroll
    for (int j = 0; j < 16; j++) {
        float xv = xs[j];
        float4 w0 = sw4[j*4+0], w1 = sw4[j*4+1], w2 = sw4[j*4+2], w3 = sw4[j*4+3];
        a0.x = fmaf(xv, w0.x, a0.x); a0.y = fmaf(xv, w0.y, a0.y);
        a0.z = fmaf(xv, w0.z, a0.z); a0.w = fmaf(xv, w0.w, a0.w);
        a1.x = fmaf(xv, w1.x, a1.x); a1.y = fmaf(xv, w1.y, a1.y);
        a1.z = fmaf(xv, w1.z, a1.z); a1.w = fmaf(xv, w1.w, a1.w);
        a2.x = fmaf(xv, w2.x, a2.x); a2.y = fmaf(xv, w2.y, a2.y);
        a2.z = fmaf(xv, w2.z, a2.z); a2.w = fmaf(xv, w2.w, a2.w);
        a3.x = fmaf(xv, w3.x, a3.x); a3.y = fmaf(xv, w3.y, a3.y);
        a3.z = fmaf(xv, w3.z, a3.z); a3.w = fmaf(xv, w3.w, a3.w);
    }
    float4* P = (float4*)((isU ? g_P_u : g_P_i) + ((size_t)r * N + n) * 16);
    P[0] = a0; P[1] = a1; P[2] = a2; P[3] = a3;
}

// ---------------- fused kernel: rproj blocks (x < RP_BLOCKS) + phase1 blocks ----------------
// rproj first so its FMA-heavy blocks start early and overlap phase1's DRAM waves.
__global__ __launch_bounds__(256) void fused_edge_kernel(
    const float* __restrict__ user_h,     const float* __restrict__ item_h,
    const float* __restrict__ user_hsum,  const float* __restrict__ item_hsum,
    const float* __restrict__ review_feat,
    const float* __restrict__ prototypes, const float* __restrict__ eta,
    const float* __restrict__ review_w_fwd, const float* __restrict__ review_w_rev,
    const int*   __restrict__ rows,       const int*   __restrict__ cols)
{
    __shared__ union {
        float proto[256];
        struct { float wt[32 * 68]; float4 rf[64 * 17]; } rp;
    } sm;

    const int r = blockIdx.y;
    const int tid = threadIdx.x;

    if (blockIdx.x < RP_BLOCKS) {
        // ================= rproj path (R2 shape: 8 warps x 8 edges) =================
        for (int i = tid; i < 2048; i += 256) {
            int o = i & 31, j = i >> 5;
            float w = (o < 16) ? review_w_fwd[r * 1024 + j * 16 + o]
                               : review_w_rev[r * 1024 + j * 16 + (o - 16)];
            sm.rp.wt[o * 68 + j] = w;
        }
        const int e0 = blockIdx.x * 64;
        for (int i = tid; i < 1024; i += 256) {
            int e = i >> 4, jq = i & 15;
            int eg = e0 + e;
            float4 v = {0,0,0,0};
            if (eg < E_N)
                v = *(const float4*)(review_feat + ((size_t)r * E_N + eg) * 256 + 128 + jq * 4);
            sm.rp.rf[e * 17 + jq] = v;
        }
        __syncthreads();

        const int lane = tid & 31;
        const int warp = tid >> 5;
        const int eb = warp * 8;
        float acc[8] = {0,0,0,0,0,0,0,0};
        const float4* wt4 = (const float4*)(sm.rp.wt + lane * 68);
#pragma unroll
        for (int jq = 0; jq < 16; jq++) {
            float4 wv = wt4[jq];
#pragma unroll
            for (int ee = 0; ee < 8; ee++) {
                float4 rv = sm.rp.rf[(eb + ee) * 17 + jq];
                acc[ee] = fmaf(rv.x, wv.x, acc[ee]);
                acc[ee] = fmaf(rv.y, wv.y, acc[ee]);
                acc[ee] = fmaf(rv.z, wv.z, acc[ee]);
                acc[ee] = fmaf(rv.w, wv.w, acc[ee]);
            }
        }
#pragma unroll
        for (int ee = 0; ee < 8; ee++) {
            int eg = e0 + eb + ee;
            if (eg < E_N)
                g_m[((size_t)r * E_N + eg) * 32 + lane] = acc[ee];
        }
        return;
    }

    // ================= phase1 path (ead) =================
    if (tid < 256) sm.proto[tid] = prototypes[tid];
    __syncthreads();

    const int lane = tid & 31;
    const int warp = tid >> 5;
    const int e = (blockIdx.x - RP_BLOCKS) * 8 + warp;
    if (e >= E_N) return;

    const size_t idx = (size_t)r * E_N + e;
    const int row = rows[idx];
    const int col = cols[idx];

    const int dh = lane & 15;
    float hval;
    if (lane < 16) hval = user_h[((size_t)r * U_N + row) * 16 + dh];
    else           hval = item_h[((size_t)r * I_N + col) * 16 + dh];
    float othv = __shfl_xor_sync(0xffffffffu, hval, 16);
    float dot = red16(hval * othv);
    float invnu = g_invn_u[(size_t)r * U_N + row];
    float invni = g_invn_i[(size_t)r * I_N + col];
    float sim_k = 2.0f * dot * invnu * invni;

    const float* uh = user_hsum + ((size_t)r * U_N + row) * 64;
    const float* ih = item_hsum + ((size_t)r * I_N + col) * 64;
    float p1 = red16(uh[lane] * ih[lane]);
    float p2 = red16(uh[lane + 32] * ih[lane + 32]);
    float eh = __expf(2.0f * p1) + __expf(2.0f * p2);
    float Ssim = eh + __shfl_xor_sync(0xffffffffu, eh, 16);
    float exp_sim = __expf(sim_k) / Ssim;

    const float* rf = review_feat + idx * 256;
    float ad0 = red32(fmaf(__ldcs(rf + lane),       sm.proto[lane],       __ldcs(rf + 32 + lane)  * sm.proto[32 + lane]));
    float ad1 = red32(fmaf(__ldcs(rf + 64 + lane),  sm.proto[64 + lane],  __ldcs(rf + 96 + lane)  * sm.proto[96 + lane]));
    float ad2 = red32(fmaf(__ldcs(rf + 128 + lane), sm.proto[128 + lane], __ldcs(rf + 160 + lane) * sm.proto[160 + lane]));
    float ad3 = red32(fmaf(__ldcs(rf + 192 + lane), sm.proto[192 + lane], __ldcs(rf + 224 + lane) * sm.proto[224 + lane]));

    float Sad = __expf(2.0f * ad0) + __expf(2.0f * ad1) +
                __expf(2.0f * ad2) + __expf(2.0f * ad3);
    float ead = __expf(2.0f * ad2) / Sad;                  // KF = 2

    float g = 1.0f / (1.0f + __expf(-eta[idx]));
    ead = g * ead + (1.0f - g) * exp_sim;

    if (lane == 0) {
        g_ead[idx] = ead;
        atomicAdd(&g_norm_u[row], ead);
        atomicAdd(&g_norm_i[col], ead);
    }
}

// ---------------- kernel 2: weight + gather P + vectorized RED scatter ----------------
__global__ __launch_bounds__(256) void phase2_kernel(
    const int* __restrict__ rows, const int* __restrict__ cols,
    float* __restrict__ int_dist_out)
{
    const int t = blockIdx.x * 256 + threadIdx.x;
    const int e = t >> 3;
    const int q = t & 7;
    if (e >= E_N) return;
    const int r = blockIdx.y;
    const size_t idx = (size_t)r * E_N + e;

    const int row = rows[idx];
    const int col = cols[idx];
    const float ead = g_ead[idx];
    const float w = ead * rsqrtf(g_norm_u[row] * g_norm_i[col]);
    if (q == 0) int_dist_out[idx] = w;

    float4 m4, p4;
    float* dest;
    if (q < 4) {
        m4 = *(const float4*)(g_m + idx * 32 + q * 4);
        p4 = *(const float4*)(g_P_u + ((size_t)r * U_N + row) * 16 + q * 4);
        dest = g_ifeat + col * 16 + q * 4;
    } else {
        const int qq = q - 4;
        m4 = *(const float4*)(g_m + idx * 32 + 16 + qq * 4);
        p4 = *(const float4*)(g_P_i + ((size_t)r * I_N + col) * 16 + qq * 4);
        dest = g_ufeat + row * 16 + qq * 4;
    }
    float4 mv;
    mv.x = (m4.x + p4.x) * w;
    mv.y = (m4.y + p4.y) * w;
    mv.z = (m4.z + p4.z) * w;
    mv.w = (m4.w + p4.w) * w;
    red_v4(dest, mv);
}

// ---------------- kernel 3: leaky + FC, weights in registers ----------------
#define NB_U ((U_N + 63) / 64)
#define NB_I ((I_N + 63) / 64)
__global__ __launch_bounds__(256) void fc_kernel(
    const float* __restrict__ ufc_w, const float* __restrict__ ufc_b,
    const float* __restrict__ ifc_w, const float* __restrict__ ifc_b,
    float* __restrict__ out)
{
    __shared__ float smx[64 * 17];
    const int tid = threadIdx.x;
    const bool isU = (blockIdx.x < NB_U);
    const int nb = (isU ? blockIdx.x : (blockIdx.x - NB_U)) * 64;
    const int N = isU ? U_N : I_N;
    const float* feat = isU ? g_ufeat : g_ifeat;
    const float* W = isU ? ufc_w : ifc_w;
    const float* B = isU ? ufc_b : ifc_b;
    float* outp = out + (isU ? 0 : (size_t)U_N * 64);

    for (int i = tid; i < 1024; i += 256) {
        int n = i >> 4, j = i & 15;
        int ng = nb + n;
        float x = (ng < N) ? feat[ng * 16 + j] : 0.f;
        x = (x >= 0.f) ? x : 0.1f * x;
        smx[n * 17 + j] = x;
    }
    __syncthreads();

    const int o = tid & 63;
    const int g = tid >> 6;
    float wr[16];
#pragma unroll
    for (int j = 0; j < 16; j++) wr[j] = W[j * 64 + o];
    const float b = B[o];

#pragma unroll
    for (int i = 0; i < 16; i++) {
        int n = g + i * 4;
        int ng = nb + n;
        if (ng < N) {
            float acc = b;
#pragma unroll
            for (int j = 0; j < 16; j++) acc = fmaf(smx[n * 17 + j], wr[j], acc);
            outp[(size_t)ng * 64 + o] = acc;
        }
    }
}

// ---------------- launch ----------------
extern "C" void kernel_launch(void* const* d_in, const int* in_sizes, int n_in,
                              void* d_out, int out_size)
{
    const float* user_h       = (const float*)d_in[0];
    const float* item_h       = (const float*)d_in[1];
    const float* user_hsum    = (const float*)d_in[2];
    const float* item_hsum    = (const float*)d_in[3];
    const float* review_feat  = (const float*)d_in[4];
    const float* prototypes   = (const float*)d_in[5];
    const float* eta          = (const float*)d_in[6];
    const float* node_w_fwd   = (const float*)d_in[7];
    const float* node_w_rev   = (const float*)d_in[8];
    const float* review_w_fwd = (const float*)d_in[9];
    const float* review_w_rev = (const float*)d_in[10];
    const float* ufc_w        = (const float*)d_in[11];
    const float* ufc_b        = (const float*)d_in[12];
    const float* ifc_w        = (const float*)d_in[13];
    const float* ifc_b        = (const float*)d_in[14];
    const int*   rows         = (const int*)d_in[15];
    const int*   cols         = (const int*)d_in[16];
    float* out = (float*)d_out;

    dim3 pgrid((U_N + 255) / 256, R_N, 2);
    precompute_kernel<<<pgrid, 256>>>(user_h, item_h, node_w_fwd, node_w_rev);

    dim3 fgrid(RP_BLOCKS + P1_BLOCKS, R_N);
    fused_edge_kernel<<<fgrid, 256>>>(user_h, item_h, user_hsum, item_hsum,
                                      review_feat, prototypes, eta,
                                      review_w_fwd, review_w_rev, rows, cols);

    dim3 p2grid((E_N * 8 + 255) / 256, R_N);
    phase2_kernel<<<p2grid, 256>>>(rows, cols, out + (size_t)(U_N + I_N) * OUT_N);

    fc_kernel<<<NB_U + NB_I, 256>>>(ufc_w, ufc_b, ifc_w, ifc_b, out);
}

// round 6
// speedup vs baseline: 1.1806x; 1.1806x over previous
#include <cuda_runtime.h>
#include <cstdint>

#define U_N   100000
#define I_N   50000
#define R_N   5
#define E_N   100000
#define K_N   4
#define D_N   16
#define RD_N  64
#define OUT_N 64
#define KF_N  2

// ---------------- device scratch ----------------
__device__ float g_norm_u[U_N];
__device__ float g_norm_i[I_N];
__device__ float g_ead[R_N * E_N];
__device__ float g_m[(size_t)R_N * E_N * 32];        // per edge: [0..15]=Rf_fwd, [16..31]=Rf_rev
__device__ float g_ufeat[U_N * D_N];
__device__ float g_ifeat[I_N * D_N];
__device__ float g_invn_u[R_N * U_N];
__device__ float g_invn_i[R_N * I_N];
__device__ float g_P_u[(size_t)R_N * U_N * D_N];     // user_h @ node_w_fwd
__device__ float g_P_i[(size_t)R_N * I_N * D_N];     // item_h @ node_w_rev

// ---------------- helpers ----------------
__device__ __forceinline__ float red16(float v) {
    v += __shfl_xor_sync(0xffffffffu, v, 1);
    v += __shfl_xor_sync(0xffffffffu, v, 2);
    v += __shfl_xor_sync(0xffffffffu, v, 4);
    v += __shfl_xor_sync(0xffffffffu, v, 8);
    return v;
}
__device__ __forceinline__ float red32(float v) {
    v = red16(v);
    v += __shfl_xor_sync(0xffffffffu, v, 16);
    return v;
}
__device__ __forceinline__ void red_v4(float* addr, float4 v) {
    asm volatile("red.global.add.v4.f32 [%0], {%1, %2, %3, %4};"
                 :: "l"(addr), "f"(v.x), "f"(v.y), "f"(v.z), "f"(v.w)
                 : "memory");
}
// packed f32x2 ops (FFMA2 — only reachable via PTX)
__device__ __forceinline__ unsigned long long dup2(float v) {
    unsigned long long d;
    asm("mov.b64 %0, {%1, %1};" : "=l"(d) : "f"(v));
    return d;
}
__device__ __forceinline__ unsigned long long fma2(unsigned long long a,
                                                   unsigned long long b,
                                                   unsigned long long c) {
    unsigned long long d;
    asm("fma.rn.f32x2 %0, %1, %2, %3;" : "=l"(d) : "l"(a), "l"(b), "l"(c));
    return d;
}
__device__ __forceinline__ void unpack2(unsigned long long v, float& lo, float& hi) {
    asm("mov.b64 {%0, %1}, %2;" : "=f"(lo), "=f"(hi) : "l"(v));
}

// ---------------- kernel A: invnorm + node projection + accumulator zeroing ----------------
__global__ __launch_bounds__(256) void precompute_kernel(
    const float* __restrict__ user_h, const float* __restrict__ item_h,
    const float* __restrict__ node_w_fwd, const float* __restrict__ node_w_rev)
{
    __shared__ float sw[256];
    const int r = blockIdx.y;
    const bool isU = (blockIdx.z == 0);
    const float* W = isU ? node_w_fwd : node_w_rev;
    if (threadIdx.x < 256) sw[threadIdx.x] = W[r * 256 + threadIdx.x];
    __syncthreads();

    const int N = isU ? U_N : I_N;
    const int n = blockIdx.x * 256 + threadIdx.x;
    if (n >= N) return;

    if (r == 0) {
        float4 z = {0.f, 0.f, 0.f, 0.f};
        if (isU) {
            g_norm_u[n] = 0.f;
            float4* f = (float4*)(g_ufeat + n * 16);
            f[0] = z; f[1] = z; f[2] = z; f[3] = z;
        } else {
            g_norm_i[n] = 0.f;
            float4* f = (float4*)(g_ifeat + n * 16);
            f[0] = z; f[1] = z; f[2] = z; f[3] = z;
        }
    }

    const float* h = (isU ? user_h : item_h) + ((size_t)r * N + n) * 16;
    float xs[16];
    const float4* h4 = (const float4*)h;
    float4 x0 = h4[0], x1 = h4[1], x2 = h4[2], x3 = h4[3];
    xs[0]=x0.x; xs[1]=x0.y; xs[2]=x0.z; xs[3]=x0.w;
    xs[4]=x1.x; xs[5]=x1.y; xs[6]=x1.z; xs[7]=x1.w;
    xs[8]=x2.x; xs[9]=x2.y; xs[10]=x2.z; xs[11]=x2.w;
    xs[12]=x3.x; xs[13]=x3.y; xs[14]=x3.z; xs[15]=x3.w;

    float ss = 0.f;
#pragma unroll
    for (int j = 0; j < 16; j++) ss = fmaf(xs[j], xs[j], ss);
    float invn = rsqrtf(ss);
    if (isU) g_invn_u[(size_t)r * U_N + n] = invn;
    else     g_invn_i[(size_t)r * I_N + n] = invn;

    float4 a0 = {0,0,0,0}, a1 = {0,0,0,0}, a2 = {0,0,0,0}, a3 = {0,0,0,0};
    const float4* sw4 = (const float4*)sw;
#pragma unroll
    for (int j = 0; j < 16; j++) {
        float xv = xs[j];
        float4 w0 = sw4[j*4+0], w1 = sw4[j*4+1], w2 = sw4[j*4+2], w3 = sw4[j*4+3];
        a0.x = fmaf(xv, w0.x, a0.x); a0.y = fmaf(xv, w0.y, a0.y);
        a0.z = fmaf(xv, w0.z, a0.z); a0.w = fmaf(xv, w0.w, a0.w);
        a1.x = fmaf(xv, w1.x, a1.x); a1.y = fmaf(xv, w1.y, a1.y);
        a1.z = fmaf(xv, w1.z, a1.z); a1.w = fmaf(xv, w1.w, a1.w);
        a2.x = fmaf(xv, w2.x, a2.x); a2.y = fmaf(xv, w2.y, a2.y);
        a2.z = fmaf(xv, w2.z, a2.z); a2.w = fmaf(xv, w2.w, a2.w);
        a3.x = fmaf(xv, w3.x, a3.x); a3.y = fmaf(xv, w3.y, a3.y);
        a3.z = fmaf(xv, w3.z, a3.z); a3.w = fmaf(xv, w3.w, a3.w);
    }
    float4* P = (float4*)((isU ? g_P_u : g_P_i) + ((size_t)r * N + n) * 16);
    P[0] = a0; P[1] = a1; P[2] = a2; P[3] = a3;
}

// ---------------- kernel 1: per-edge ead only (R2/R4 structure) ----------------
__global__ __launch_bounds__(256) void phase1_kernel(
    const float* __restrict__ user_h,     const float* __restrict__ item_h,
    const float* __restrict__ user_hsum,  const float* __restrict__ item_hsum,
    const float* __restrict__ review_feat,
    const float* __restrict__ prototypes, const float* __restrict__ eta,
    const int*   __restrict__ rows,       const int*   __restrict__ cols)
{
    __shared__ float sm[256];
    const int r = blockIdx.y;
    if (threadIdx.x < 256) sm[threadIdx.x] = prototypes[threadIdx.x];
    __syncthreads();

    const int lane = threadIdx.x & 31;
    const int warp = threadIdx.x >> 5;
    const int e = blockIdx.x * 8 + warp;
    if (e >= E_N) return;

    const size_t idx = (size_t)r * E_N + e;
    const int row = rows[idx];
    const int col = cols[idx];

    const int dh = lane & 15;
    float hval;
    if (lane < 16) hval = user_h[((size_t)r * U_N + row) * 16 + dh];
    else           hval = item_h[((size_t)r * I_N + col) * 16 + dh];
    float othv = __shfl_xor_sync(0xffffffffu, hval, 16);
    float dot = red16(hval * othv);
    float invnu = g_invn_u[(size_t)r * U_N + row];
    float invni = g_invn_i[(size_t)r * I_N + col];
    float sim_k = 2.0f * dot * invnu * invni;

    const float* uh = user_hsum + ((size_t)r * U_N + row) * 64;
    const float* ih = item_hsum + ((size_t)r * I_N + col) * 64;
    float p1 = red16(uh[lane] * ih[lane]);
    float p2 = red16(uh[lane + 32] * ih[lane + 32]);
    float eh = __expf(2.0f * p1) + __expf(2.0f * p2);
    float Ssim = eh + __shfl_xor_sync(0xffffffffu, eh, 16);
    float exp_sim = __expf(sim_k) / Ssim;

    const float* rf = review_feat + idx * 256;
    float ad0 = red32(fmaf(__ldcs(rf + lane),       sm[lane],       __ldcs(rf + 32 + lane)  * sm[32 + lane]));
    float ad1 = red32(fmaf(__ldcs(rf + 64 + lane),  sm[64 + lane],  __ldcs(rf + 96 + lane)  * sm[96 + lane]));
    float ad2 = red32(fmaf(__ldcs(rf + 128 + lane), sm[128 + lane], __ldcs(rf + 160 + lane) * sm[160 + lane]));
    float ad3 = red32(fmaf(__ldcs(rf + 192 + lane), sm[192 + lane], __ldcs(rf + 224 + lane) * sm[224 + lane]));

    float Sad = __expf(2.0f * ad0) + __expf(2.0f * ad1) +
                __expf(2.0f * ad2) + __expf(2.0f * ad3);
    float ead = __expf(2.0f * ad2) / Sad;                  // KF = 2

    float g = 1.0f / (1.0f + __expf(-eta[idx]));
    ead = g * ead + (1.0f - g) * exp_sim;

    if (lane == 0) {
        g_ead[idx] = ead;
        atomicAdd(&g_norm_u[row], ead);
        atomicAdd(&g_norm_i[col], ead);
    }
}

// ---------------- kernel B: review projection GEMM, f32x2-packed edge pairs ----------------
// Rf[e][o] = sum_j rf_k[e][j] * Wc[j][o], Wc = [W_rf | W_rr] (64x32).
// Block: 64 edges = 32 pairs. smem rf stored as (even,odd)-edge float2 per j:
// slot (pair p, j) -> 16B unit holds {f2(j), f2(j+1)}. Warp: 4 pairs x 32 outs.
__global__ __launch_bounds__(256) void rproj_kernel(
    const float* __restrict__ review_feat,
    const float* __restrict__ review_w_fwd, const float* __restrict__ review_w_rev)
{
    __shared__ float      smWT[32 * 68];        // [o][j], stride 68 (conflict-free LDS.128)
    __shared__ ulonglong2 smrf[32 * 33];        // [pair][j/2], stride 33 units
    const int r = blockIdx.y;
    const int tid = threadIdx.x;

    for (int i = tid; i < 2048; i += 256) {
        int o = i & 31, j = i >> 5;
        float w = (o < 16) ? review_w_fwd[r * 1024 + j * 16 + o]
                           : review_w_rev[r * 1024 + j * 16 + (o - 16)];
        smWT[o * 68 + j] = w;
    }

    const int e0 = blockIdx.x * 64;
    float* smrf_f = (float*)smrf;
    // fill: 64 edges x 16 float4 (jf chunks of 4)
    for (int i = tid; i < 1024; i += 256) {
        int e = i >> 4, q = i & 15;
        int eg = e0 + e;
        float4 v = {0,0,0,0};
        if (eg < E_N)
            v = *(const float4*)(review_feat + ((size_t)r * E_N + eg) * 256 + 128 + q * 4);
        int p = e >> 1, h = e & 1;
        int jf = q * 4;
        // float index: (p*33 + (jf>>1))*4 + (jf&1)*2 + h ; jf even here
        int base = (p * 33 + (jf >> 1)) * 4 + h;
        smrf_f[base + 0] = v.x;          // j = jf
        smrf_f[base + 2] = v.y;          // j = jf+1
        smrf_f[base + 4] = v.z;          // j = jf+2  (next 16B unit)
        smrf_f[base + 6] = v.w;          // j = jf+3
    }
    __syncthreads();

    const int lane = tid & 31;
    const int warp = tid >> 5;
    const int pbase = warp * 4;          // 4 pairs = 8 edges per warp
    unsigned long long acc2[4] = {0ull, 0ull, 0ull, 0ull};
    const float4* wt4 = (const float4*)(smWT + lane * 68);
#pragma unroll
    for (int jq = 0; jq < 16; jq++) {
        float4 wv = wt4[jq];
        unsigned long long w0 = dup2(wv.x), w1 = dup2(wv.y);
        unsigned long long w2 = dup2(wv.z), w3 = dup2(wv.w);
#pragma unroll
        for (int pp = 0; pp < 4; pp++) {
            const ulonglong2* rp = smrf + (pbase + pp) * 33 + jq * 2;
            ulonglong2 ra = rp[0];       // j = 4jq, 4jq+1 (packed even/odd edge)
            ulonglong2 rb = rp[1];       // j = 4jq+2, 4jq+3
            acc2[pp] = fma2(ra.x, w0, acc2[pp]);
            acc2[pp] = fma2(ra.y, w1, acc2[pp]);
            acc2[pp] = fma2(rb.x, w2, acc2[pp]);
            acc2[pp] = fma2(rb.y, w3, acc2[pp]);
        }
    }
#pragma unroll
    for (int pp = 0; pp < 4; pp++) {
        float lo, hi;
        unpack2(acc2[pp], lo, hi);
        int e_even = e0 + warp * 8 + 2 * pp;
        if (e_even < E_N)
            g_m[((size_t)r * E_N + e_even) * 32 + lane] = lo;
        if (e_even + 1 < E_N)
            g_m[((size_t)r * E_N + e_even + 1) * 32 + lane] = hi;
    }
}

// ---------------- kernel 2: weight + gather P + vectorized RED scatter ----------------
__global__ __launch_bounds__(256) void phase2_kernel(
    const int* __restrict__ rows, const int* __restrict__ cols,
    float* __restrict__ int_dist_out)
{
    const int t = blockIdx.x * 256 + threadIdx.x;
    const int e = t >> 3;
    const int q = t & 7;
    if (e >= E_N) return;
    const int r = blockIdx.y;
    const size_t idx = (size_t)r * E_N + e;

    const int row = rows[idx];
    const int col = cols[idx];
    const float ead = g_ead[idx];
    const float w = ead * rsqrtf(g_norm_u[row] * g_norm_i[col]);
    if (q == 0) int_dist_out[idx] = w;

    float4 m4, p4;
    float* dest;
    if (q < 4) {
        m4 = *(const float4*)(g_m + idx * 32 + q * 4);
        p4 = *(const float4*)(g_P_u + ((size_t)r * U_N + row) * 16 + q * 4);
        dest = g_ifeat + col * 16 + q * 4;
    } else {
        const int qq = q - 4;
        m4 = *(const float4*)(g_m + idx * 32 + 16 + qq * 4);
        p4 = *(const float4*)(g_P_i + ((size_t)r * I_N + col) * 16 + qq * 4);
        dest = g_ufeat + row * 16 + qq * 4;
    }
    float4 mv;
    mv.x = (m4.x + p4.x) * w;
    mv.y = (m4.y + p4.y) * w;
    mv.z = (m4.z + p4.z) * w;
    mv.w = (m4.w + p4.w) * w;
    red_v4(dest, mv);
}

// ---------------- kernel 3: leaky + FC, weights in registers ----------------
#define NB_U ((U_N + 63) / 64)
#define NB_I ((I_N + 63) / 64)
__global__ __launch_bounds__(256) void fc_kernel(
    const float* __restrict__ ufc_w, const float* __restrict__ ufc_b,
    const float* __restrict__ ifc_w, const float* __restrict__ ifc_b,
    float* __restrict__ out)
{
    __shared__ float smx[64 * 17];
    const int tid = threadIdx.x;
    const bool isU = (blockIdx.x < NB_U);
    const int nb = (isU ? blockIdx.x : (blockIdx.x - NB_U)) * 64;
    const int N = isU ? U_N : I_N;
    const float* feat = isU ? g_ufeat : g_ifeat;
    const float* W = isU ? ufc_w : ifc_w;
    const float* B = isU ? ufc_b : ifc_b;
    float* outp = out + (isU ? 0 : (size_t)U_N * 64);

    for (int i = tid; i < 1024; i += 256) {
        int n = i >> 4, j = i & 15;
        int ng = nb + n;
        float x = (ng < N) ? feat[ng * 16 + j] : 0.f;
        x = (x >= 0.f) ? x : 0.1f * x;
        smx[n * 17 + j] = x;
    }
    __syncthreads();

    const int o = tid & 63;
    const int g = tid >> 6;
    float wr[16];
#pragma unroll
    for (int j = 0; j < 16; j++) wr[j] = W[j * 64 + o];
    const float b = B[o];

#pragma unroll
    for (int i = 0; i < 16; i++) {
        int n = g + i * 4;
        int ng = nb + n;
        if (ng < N) {
            float acc = b;
#pragma unroll
            for (int j = 0; j < 16; j++) acc = fmaf(smx[n * 17 + j], wr[j], acc);
            outp[(size_t)ng * 64 + o] = acc;
        }
    }
}

// ---------------- launch ----------------
extern "C" void kernel_launch(void* const* d_in, const int* in_sizes, int n_in,
                              void* d_out, int out_size)
{
    const float* user_h       = (const float*)d_in[0];
    const float* item_h       = (const float*)d_in[1];
    const float* user_hsum    = (const float*)d_in[2];
    const float* item_hsum    = (const float*)d_in[3];
    const float* review_feat  = (const float*)d_in[4];
    const float* prototypes   = (const float*)d_in[5];
    const float* eta          = (const float*)d_in[6];
    const float* node_w_fwd   = (const float*)d_in[7];
    const float* node_w_rev   = (const float*)d_in[8];
    const float* review_w_fwd = (const float*)d_in[9];
    const float* review_w_rev = (const float*)d_in[10];
    const float* ufc_w        = (const float*)d_in[11];
    const float* ufc_b        = (const float*)d_in[12];
    const float* ifc_w        = (const float*)d_in[13];
    const float* ifc_b        = (const float*)d_in[14];
    const int*   rows         = (const int*)d_in[15];
    const int*   cols         = (const int*)d_in[16];
    float* out = (float*)d_out;

    dim3 pgrid((U_N + 255) / 256, R_N, 2);
    precompute_kernel<<<pgrid, 256>>>(user_h, item_h, node_w_fwd, node_w_rev);

    dim3 egrid(E_N / 8, R_N);
    phase1_kernel<<<egrid, 256>>>(user_h, item_h, user_hsum, item_hsum,
                                  review_feat, prototypes, eta, rows, cols);

    dim3 bgrid((E_N + 63) / 64, R_N);
    rproj_kernel<<<bgrid, 256>>>(review_feat, review_w_fwd, review_w_rev);

    dim3 p2grid((E_N * 8 + 255) / 256, R_N);
    phase2_kernel<<<p2grid, 256>>>(rows, cols, out + (size_t)(U_N + I_N) * OUT_N);

    fc_kernel<<<NB_U + NB_I, 256>>>(ufc_w, ufc_b, ifc_w, ifc_b, out);
}

// round 7
// speedup vs baseline: 1.2315x; 1.0431x over previous
#include <cuda_runtime.h>
#include <cstdint>

#define U_N   100000
#define I_N   50000
#define R_N   5
#define E_N   100000
#define K_N   4
#define D_N   16
#define RD_N  64
#define OUT_N 64
#define KF_N  2

// ---------------- device scratch ----------------
__device__ float g_norm_u[U_N];
__device__ float g_norm_i[I_N];
__device__ float g_ead[R_N * E_N];
__device__ float g_m[(size_t)R_N * E_N * 32];        // per edge: [0..15]=Rf_fwd, [16..31]=Rf_rev
__device__ float g_ufeat[U_N * D_N];
__device__ float g_ifeat[I_N * D_N];
__device__ float g_invn_u[R_N * U_N];
__device__ float g_invn_i[R_N * I_N];
__device__ float g_P_u[(size_t)R_N * U_N * D_N];     // user_h @ node_w_fwd
__device__ float g_P_i[(size_t)R_N * I_N * D_N];     // item_h @ node_w_rev

// ---------------- helpers ----------------
__device__ __forceinline__ float red16(float v) {
    v += __shfl_xor_sync(0xffffffffu, v, 1);
    v += __shfl_xor_sync(0xffffffffu, v, 2);
    v += __shfl_xor_sync(0xffffffffu, v, 4);
    v += __shfl_xor_sync(0xffffffffu, v, 8);
    return v;
}
__device__ __forceinline__ void red_v4(float* addr, float4 v) {
    asm volatile("red.global.add.v4.f32 [%0], {%1, %2, %3, %4};"
                 :: "l"(addr), "f"(v.x), "f"(v.y), "f"(v.z), "f"(v.w)
                 : "memory");
}
// packed f32x2 ops (FFMA2 — only reachable via PTX)
__device__ __forceinline__ unsigned long long dup2(float v) {
    unsigned long long d;
    asm("mov.b64 %0, {%1, %1};" : "=l"(d) : "f"(v));
    return d;
}
__device__ __forceinline__ unsigned long long fma2(unsigned long long a,
                                                   unsigned long long b,
                                                   unsigned long long c) {
    unsigned long long d;
    asm("fma.rn.f32x2 %0, %1, %2, %3;" : "=l"(d) : "l"(a), "l"(b), "l"(c));
    return d;
}
__device__ __forceinline__ void unpack2(unsigned long long v, float& lo, float& hi) {
    asm("mov.b64 {%0, %1}, %2;" : "=f"(lo), "=f"(hi) : "l"(v));
}

// ---------------- kernel A: invnorm + node projection + accumulator zeroing ----------------
__global__ __launch_bounds__(256) void precompute_kernel(
    const float* __restrict__ user_h, const float* __restrict__ item_h,
    const float* __restrict__ node_w_fwd, const float* __restrict__ node_w_rev)
{
    __shared__ float sw[256];
    const int r = blockIdx.y;
    const bool isU = (blockIdx.z == 0);
    const float* W = isU ? node_w_fwd : node_w_rev;
    if (threadIdx.x < 256) sw[threadIdx.x] = W[r * 256 + threadIdx.x];
    __syncthreads();

    const int N = isU ? U_N : I_N;
    const int n = blockIdx.x * 256 + threadIdx.x;
    if (n >= N) return;

    if (r == 0) {
        float4 z = {0.f, 0.f, 0.f, 0.f};
        if (isU) {
            g_norm_u[n] = 0.f;
            float4* f = (float4*)(g_ufeat + n * 16);
            f[0] = z; f[1] = z; f[2] = z; f[3] = z;
        } else {
            g_norm_i[n] = 0.f;
            float4* f = (float4*)(g_ifeat + n * 16);
            f[0] = z; f[1] = z; f[2] = z; f[3] = z;
        }
    }

    const float* h = (isU ? user_h : item_h) + ((size_t)r * N + n) * 16;
    float xs[16];
    const float4* h4 = (const float4*)h;
    float4 x0 = h4[0], x1 = h4[1], x2 = h4[2], x3 = h4[3];
    xs[0]=x0.x; xs[1]=x0.y; xs[2]=x0.z; xs[3]=x0.w;
    xs[4]=x1.x; xs[5]=x1.y; xs[6]=x1.z; xs[7]=x1.w;
    xs[8]=x2.x; xs[9]=x2.y; xs[10]=x2.z; xs[11]=x2.w;
    xs[12]=x3.x; xs[13]=x3.y; xs[14]=x3.z; xs[15]=x3.w;

    float ss = 0.f;
#pragma unroll
    for (int j = 0; j < 16; j++) ss = fmaf(xs[j], xs[j], ss);
    float invn = rsqrtf(ss);
    if (isU) g_invn_u[(size_t)r * U_N + n] = invn;
    else     g_invn_i[(size_t)r * I_N + n] = invn;

    float4 a0 = {0,0,0,0}, a1 = {0,0,0,0}, a2 = {0,0,0,0}, a3 = {0,0,0,0};
    const float4* sw4 = (const float4*)sw;
#pragma unroll
    for (int j = 0; j < 16; j++) {
        float xv = xs[j];
        float4 w0 = sw4[j*4+0], w1 = sw4[j*4+1], w2 = sw4[j*4+2], w3 = sw4[j*4+3];
        a0.x = fmaf(xv, w0.x, a0.x); a0.y = fmaf(xv, w0.y, a0.y);
        a0.z = fmaf(xv, w0.z, a0.z); a0.w = fmaf(xv, w0.w, a0.w);
        a1.x = fmaf(xv, w1.x, a1.x); a1.y = fmaf(xv, w1.y, a1.y);
        a1.z = fmaf(xv, w1.z, a1.z); a1.w = fmaf(xv, w1.w, a1.w);
        a2.x = fmaf(xv, w2.x, a2.x); a2.y = fmaf(xv, w2.y, a2.y);
        a2.z = fmaf(xv, w2.z, a2.z); a2.w = fmaf(xv, w2.w, a2.w);
        a3.x = fmaf(xv, w3.x, a3.x); a3.y = fmaf(xv, w3.y, a3.y);
        a3.z = fmaf(xv, w3.z, a3.z); a3.w = fmaf(xv, w3.w, a3.w);
    }
    float4* P = (float4*)((isU ? g_P_u : g_P_i) + ((size_t)r * N + n) * 16);
    P[0] = a0; P[1] = a1; P[2] = a2; P[3] = a3;
}

// ---------------- kernel 1: per-edge ead, wide-load layout ----------------
// one warp per edge; all bulk data via LDG.128 + short subgroup reductions.
__global__ __launch_bounds__(256) void phase1_kernel(
    const float* __restrict__ user_h,     const float* __restrict__ item_h,
    const float* __restrict__ user_hsum,  const float* __restrict__ item_hsum,
    const float* __restrict__ review_feat,
    const float* __restrict__ prototypes, const float* __restrict__ eta,
    const int*   __restrict__ rows,       const int*   __restrict__ cols)
{
    __shared__ float sm[256];
    const int r = blockIdx.y;
    if (threadIdx.x < 256) sm[threadIdx.x] = prototypes[threadIdx.x];
    __syncthreads();

    const int lane = threadIdx.x & 31;
    const int warp = threadIdx.x >> 5;
    const int e = blockIdx.x * 8 + warp;
    if (e >= E_N) return;

    const size_t idx = (size_t)r * E_N + e;
    const int row = rows[idx];
    const int col = cols[idx];
    const unsigned FULL = 0xffffffffu;

    // ---- issue all wide loads up front (max MLP) ----
    // node feature: lanes 0-15 user dims, 16-31 item dims (1 LDG.32)
    const int dh = lane & 15;
    float hval;
    if (lane < 16) hval = __ldg(user_h + ((size_t)r * U_N + row) * 16 + dh);
    else           hval = __ldg(item_h + ((size_t)r * I_N + col) * 16 + dh);

    // hsum: lanes 0-15 hold uh[4l..4l+3], lanes 16-31 ih[4(l-16)..]
    const float* uh = user_hsum + ((size_t)r * U_N + row) * 64;
    const float* ih = item_hsum + ((size_t)r * I_N + col) * 64;
    float4 hs;
    if (lane < 16) hs = *(const float4*)(uh + 4 * lane);
    else           hs = *(const float4*)(ih + 4 * (lane - 16));

    // review row: lane owns rf[8*lane .. 8*lane+7] (2 LDG.128, streaming)
    const float4* rf4 = (const float4*)(review_feat + idx * 256);
    float4 ra = __ldcs(rf4 + lane * 2);
    float4 rb = __ldcs(rf4 + lane * 2 + 1);

    const float invnu = g_invn_u[(size_t)r * U_N + row];
    const float invni = g_invn_i[(size_t)r * I_N + col];
    const float etav = eta[idx];

    // ---- sim_k: normalized node dot ----
    float othv = __shfl_xor_sync(FULL, hval, 16);
    float dot = red16(hval * othv);
    float sim_k = 2.0f * dot * invnu * invni;

    // ---- sim_all: pair halves, dot4, reduce within 4-lane k-groups ----
    float4 oth;
    oth.x = __shfl_xor_sync(FULL, hs.x, 16);
    oth.y = __shfl_xor_sync(FULL, hs.y, 16);
    oth.z = __shfl_xor_sync(FULL, hs.z, 16);
    oth.w = __shfl_xor_sync(FULL, hs.w, 16);
    float p = hs.x * oth.x + hs.y * oth.y + hs.z * oth.z + hs.w * oth.w;
    p += __shfl_xor_sync(FULL, p, 1);
    p += __shfl_xor_sync(FULL, p, 2);      // 4-lane group (lane&15)>>2 == k has p_k
    float ek = __expf(2.0f * p);
    float Ssim = ek;
    Ssim += __shfl_xor_sync(FULL, Ssim, 4);
    Ssim += __shfl_xor_sync(FULL, Ssim, 8); // sum over the 4 k-groups (halves duplicate)
    float exp_sim = __expf(sim_k) / Ssim;

    // ---- prototype dots: 8-lane group g covers k=g ----
    const float4* pr4 = (const float4*)sm;
    float4 pa = pr4[lane * 2];
    float4 pb = pr4[lane * 2 + 1];
    float ad = ra.x * pa.x + ra.y * pa.y + ra.z * pa.z + ra.w * pa.w
             + rb.x * pb.x + rb.y * pb.y + rb.z * pb.z + rb.w * pb.w;
    ad += __shfl_xor_sync(FULL, ad, 1);
    ad += __shfl_xor_sync(FULL, ad, 2);
    ad += __shfl_xor_sync(FULL, ad, 4);    // group lane>>3 has ad_k
    float eab = __expf(2.0f * ad);
    float Sad = eab;
    Sad += __shfl_xor_sync(FULL, Sad, 8);
    Sad += __shfl_xor_sync(FULL, Sad, 16); // all lanes: e0+e1+e2+e3
    float e2 = __shfl_sync(FULL, eab, 16); // group 2 (KF=2) exp value
    float ead = e2 / Sad;

    float g = 1.0f / (1.0f + __expf(-etav));
    ead = g * ead + (1.0f - g) * exp_sim;

    if (lane == 0) {
        g_ead[idx] = ead;
        atomicAdd(&g_norm_u[row], ead);
        atomicAdd(&g_norm_i[col], ead);
    }
}

// ---------------- kernel B: review projection GEMM, f32x2-packed edge pairs ----------------
__global__ __launch_bounds__(256) void rproj_kernel(
    const float* __restrict__ review_feat,
    const float* __restrict__ review_w_fwd, const float* __restrict__ review_w_rev)
{
    __shared__ float      smWT[32 * 68];        // [o][j], stride 68 (conflict-free LDS.128)
    __shared__ ulonglong2 smrf[32 * 33];        // [pair][j/2], stride 33 units
    const int r = blockIdx.y;
    const int tid = threadIdx.x;

    for (int i = tid; i < 2048; i += 256) {
        int o = i & 31, j = i >> 5;
        float w = (o < 16) ? review_w_fwd[r * 1024 + j * 16 + o]
                           : review_w_rev[r * 1024 + j * 16 + (o - 16)];
        smWT[o * 68 + j] = w;
    }

    const int e0 = blockIdx.x * 64;
    float* smrf_f = (float*)smrf;
    for (int i = tid; i < 1024; i += 256) {
        int e = i >> 4, q = i & 15;
        int eg = e0 + e;
        float4 v = {0,0,0,0};
        if (eg < E_N)
            v = *(const float4*)(review_feat + ((size_t)r * E_N + eg) * 256 + 128 + q * 4);
        int p = e >> 1, h = e & 1;
        int jf = q * 4;
        int base = (p * 33 + (jf >> 1)) * 4 + h;
        smrf_f[base + 0] = v.x;
        smrf_f[base + 2] = v.y;
        smrf_f[base + 4] = v.z;
        smrf_f[base + 6] = v.w;
    }
    __syncthreads();

    const int lane = tid & 31;
    const int warp = tid >> 5;
    const int pbase = warp * 4;
    unsigned long long acc2[4] = {0ull, 0ull, 0ull, 0ull};
    const float4* wt4 = (const float4*)(smWT + lane * 68);
#pragma unroll
    for (int jq = 0; jq < 16; jq++) {
        float4 wv = wt4[jq];
        unsigned long long w0 = dup2(wv.x), w1 = dup2(wv.y);
        unsigned long long w2 = dup2(wv.z), w3 = dup2(wv.w);
#pragma unroll
        for (int pp = 0; pp < 4; pp++) {
            const ulonglong2* rp = smrf + (pbase + pp) * 33 + jq * 2;
            ulonglong2 ra = rp[0];
            ulonglong2 rb = rp[1];
            acc2[pp] = fma2(ra.x, w0, acc2[pp]);
            acc2[pp] = fma2(ra.y, w1, acc2[pp]);
            acc2[pp] = fma2(rb.x, w2, acc2[pp]);
            acc2[pp] = fma2(rb.y, w3, acc2[pp]);
        }
    }
#pragma unroll
    for (int pp = 0; pp < 4; pp++) {
        float lo, hi;
        unpack2(acc2[pp], lo, hi);
        int e_even = e0 + warp * 8 + 2 * pp;
        if (e_even < E_N)
            g_m[((size_t)r * E_N + e_even) * 32 + lane] = lo;
        if (e_even + 1 < E_N)
            g_m[((size_t)r * E_N + e_even + 1) * 32 + lane] = hi;
    }
}

// ---------------- kernel 2: weight + gather P + vectorized RED scatter ----------------
__global__ __launch_bounds__(256) void phase2_kernel(
    const int* __restrict__ rows, const int* __restrict__ cols,
    float* __restrict__ int_dist_out)
{
    const int t = blockIdx.x * 256 + threadIdx.x;
    const int e = t >> 3;
    const int q = t & 7;
    if (e >= E_N) return;
    const int r = blockIdx.y;
    const size_t idx = (size_t)r * E_N + e;

    const int row = rows[idx];
    const int col = cols[idx];
    const float ead = g_ead[idx];
    const float w = ead * rsqrtf(g_norm_u[row] * g_norm_i[col]);
    if (q == 0) int_dist_out[idx] = w;

    float4 m4, p4;
    float* dest;
    if (q < 4) {
        m4 = *(const float4*)(g_m + idx * 32 + q * 4);
        p4 = *(const float4*)(g_P_u + ((size_t)r * U_N + row) * 16 + q * 4);
        dest = g_ifeat + col * 16 + q * 4;
    } else {
        const int qq = q - 4;
        m4 = *(const float4*)(g_m + idx * 32 + 16 + qq * 4);
        p4 = *(const float4*)(g_P_i + ((size_t)r * I_N + col) * 16 + qq * 4);
        dest = g_ufeat + row * 16 + qq * 4;
    }
    float4 mv;
    mv.x = (m4.x + p4.x) * w;
    mv.y = (m4.y + p4.y) * w;
    mv.z = (m4.z + p4.z) * w;
    mv.w = (m4.w + p4.w) * w;
    red_v4(dest, mv);
}

// ---------------- kernel 3: leaky + FC, weights in registers ----------------
#define NB_U ((U_N + 63) / 64)
#define NB_I ((I_N + 63) / 64)
__global__ __launch_bounds__(256) void fc_kernel(
    const float* __restrict__ ufc_w, const float* __restrict__ ufc_b,
    const float* __restrict__ ifc_w, const float* __restrict__ ifc_b,
    float* __restrict__ out)
{
    __shared__ float smx[64 * 17];
    const int tid = threadIdx.x;
    const bool isU = (blockIdx.x < NB_U);
    const int nb = (isU ? blockIdx.x : (blockIdx.x - NB_U)) * 64;
    const int N = isU ? U_N : I_N;
    const float* feat = isU ? g_ufeat : g_ifeat;
    const float* W = isU ? ufc_w : ifc_w;
    const float* B = isU ? ufc_b : ifc_b;
    float* outp = out + (isU ? 0 : (size_t)U_N * 64);

    for (int i = tid; i < 1024; i += 256) {
        int n = i >> 4, j = i & 15;
        int ng = nb + n;
        float x = (ng < N) ? feat[ng * 16 + j] : 0.f;
        x = (x >= 0.f) ? x : 0.1f * x;
        smx[n * 17 + j] = x;
    }
    __syncthreads();

    const int o = tid & 63;
    const int g = tid >> 6;
    float wr[16];
#pragma unroll
    for (int j = 0; j < 16; j++) wr[j] = W[j * 64 + o];
    const float b = B[o];

#pragma unroll
    for (int i = 0; i < 16; i++) {
        int n = g + i * 4;
        int ng = nb + n;
        if (ng < N) {
            float acc = b;
#pragma unroll
            for (int j = 0; j < 16; j++) acc = fmaf(smx[n * 17 + j], wr[j], acc);
            outp[(size_t)ng * 64 + o] = acc;
        }
    }
}

// ---------------- launch ----------------
extern "C" void kernel_launch(void* const* d_in, const int* in_sizes, int n_in,
                              void* d_out, int out_size)
{
    const float* user_h       = (const float*)d_in[0];
    const float* item_h       = (const float*)d_in[1];
    const float* user_hsum    = (const float*)d_in[2];
    const float* item_hsum    = (const float*)d_in[3];
    const float* review_feat  = (const float*)d_in[4];
    const float* prototypes   = (const float*)d_in[5];
    const float* eta          = (const float*)d_in[6];
    const float* node_w_fwd   = (const float*)d_in[7];
    const float* node_w_rev   = (const float*)d_in[8];
    const float* review_w_fwd = (const float*)d_in[9];
    const float* review_w_rev = (const float*)d_in[10];
    const float* ufc_w        = (const float*)d_in[11];
    const float* ufc_b        = (const float*)d_in[12];
    const float* ifc_w        = (const float*)d_in[13];
    const float* ifc_b        = (const float*)d_in[14];
    const int*   rows         = (const int*)d_in[15];
    const int*   cols         = (const int*)d_in[16];
    float* out = (float*)d_out;

    dim3 pgrid((U_N + 255) / 256, R_N, 2);
    precompute_kernel<<<pgrid, 256>>>(user_h, item_h, node_w_fwd, node_w_rev);

    dim3 egrid(E_N / 8, R_N);
    phase1_kernel<<<egrid, 256>>>(user_h, item_h, user_hsum, item_hsum,
                                  review_feat, prototypes, eta, rows, cols);

    dim3 bgrid((E_N + 63) / 64, R_N);
    rproj_kernel<<<bgrid, 256>>>(review_feat, review_w_fwd, review_w_rev);

    dim3 p2grid((E_N * 8 + 255) / 256, R_N);
    phase2_kernel<<<p2grid, 256>>>(rows, cols, out + (size_t)(U_N + I_N) * OUT_N);

    fc_kernel<<<NB_U + NB_I, 256>>>(ufc_w, ufc_b, ifc_w, ifc_b, out);
}

// round 8
// speedup vs baseline: 1.2990x; 1.0548x over previous
#include <cuda_runtime.h>
#include <cstdint>

#define U_N   100000
#define I_N   50000
#define R_N   5
#define E_N   100000
#define K_N   4
#define D_N   16
#define RD_N  64
#define OUT_N 64
#define KF_N  2

// ---------------- device scratch ----------------
__device__ float g_norm_u[U_N];
__device__ float g_norm_i[I_N];
__device__ float g_ead[R_N * E_N];
__device__ float g_ufeat[U_N * D_N];
__device__ float g_ifeat[I_N * D_N];
__device__ float g_invn_u[R_N * U_N];
__device__ float g_invn_i[R_N * I_N];
__device__ float g_P_u[(size_t)R_N * U_N * D_N];     // user_h @ node_w_fwd
__device__ float g_P_i[(size_t)R_N * I_N * D_N];     // item_h @ node_w_rev

// ---------------- helpers ----------------
__device__ __forceinline__ float red16(float v) {
    v += __shfl_xor_sync(0xffffffffu, v, 1);
    v += __shfl_xor_sync(0xffffffffu, v, 2);
    v += __shfl_xor_sync(0xffffffffu, v, 4);
    v += __shfl_xor_sync(0xffffffffu, v, 8);
    return v;
}
__device__ __forceinline__ void red_v4(float* addr, float4 v) {
    asm volatile("red.global.add.v4.f32 [%0], {%1, %2, %3, %4};"
                 :: "l"(addr), "f"(v.x), "f"(v.y), "f"(v.z), "f"(v.w)
                 : "memory");
}
// packed f32x2 ops (FFMA2 — only reachable via PTX)
__device__ __forceinline__ unsigned long long dup2(float v) {
    unsigned long long d;
    asm("mov.b64 %0, {%1, %1};" : "=l"(d) : "f"(v));
    return d;
}
__device__ __forceinline__ unsigned long long fma2(unsigned long long a,
                                                   unsigned long long b,
                                                   unsigned long long c) {
    unsigned long long d;
    asm("fma.rn.f32x2 %0, %1, %2, %3;" : "=l"(d) : "l"(a), "l"(b), "l"(c));
    return d;
}
__device__ __forceinline__ void unpack2(unsigned long long v, float& lo, float& hi) {
    asm("mov.b64 {%0, %1}, %2;" : "=f"(lo), "=f"(hi) : "l"(v));
}

// ---------------- kernel A: invnorm + node projection + accumulator zeroing ----------------
__global__ __launch_bounds__(256) void precompute_kernel(
    const float* __restrict__ user_h, const float* __restrict__ item_h,
    const float* __restrict__ node_w_fwd, const float* __restrict__ node_w_rev)
{
    __shared__ float sw[256];
    const int r = blockIdx.y;
    const bool isU = (blockIdx.z == 0);
    const float* W = isU ? node_w_fwd : node_w_rev;
    if (threadIdx.x < 256) sw[threadIdx.x] = W[r * 256 + threadIdx.x];
    __syncthreads();

    const int N = isU ? U_N : I_N;
    const int n = blockIdx.x * 256 + threadIdx.x;
    if (n >= N) return;

    if (r == 0) {
        float4 z = {0.f, 0.f, 0.f, 0.f};
        if (isU) {
            g_norm_u[n] = 0.f;
            float4* f = (float4*)(g_ufeat + n * 16);
            f[0] = z; f[1] = z; f[2] = z; f[3] = z;
        } else {
            g_norm_i[n] = 0.f;
            float4* f = (float4*)(g_ifeat + n * 16);
            f[0] = z; f[1] = z; f[2] = z; f[3] = z;
        }
    }

    const float* h = (isU ? user_h : item_h) + ((size_t)r * N + n) * 16;
    float xs[16];
    const float4* h4 = (const float4*)h;
    float4 x0 = h4[0], x1 = h4[1], x2 = h4[2], x3 = h4[3];
    xs[0]=x0.x; xs[1]=x0.y; xs[2]=x0.z; xs[3]=x0.w;
    xs[4]=x1.x; xs[5]=x1.y; xs[6]=x1.z; xs[7]=x1.w;
    xs[8]=x2.x; xs[9]=x2.y; xs[10]=x2.z; xs[11]=x2.w;
    xs[12]=x3.x; xs[13]=x3.y; xs[14]=x3.z; xs[15]=x3.w;

    float ss = 0.f;
#pragma unroll
    for (int j = 0; j < 16; j++) ss = fmaf(xs[j], xs[j], ss);
    float invn = rsqrtf(ss);
    if (isU) g_invn_u[(size_t)r * U_N + n] = invn;
    else     g_invn_i[(size_t)r * I_N + n] = invn;

    float4 a0 = {0,0,0,0}, a1 = {0,0,0,0}, a2 = {0,0,0,0}, a3 = {0,0,0,0};
    const float4* sw4 = (const float4*)sw;
#pragma unroll
    for (int j = 0; j < 16; j++) {
        float xv = xs[j];
        float4 w0 = sw4[j*4+0], w1 = sw4[j*4+1], w2 = sw4[j*4+2], w3 = sw4[j*4+3];
        a0.x = fmaf(xv, w0.x, a0.x); a0.y = fmaf(xv, w0.y, a0.y);
        a0.z = fmaf(xv, w0.z, a0.z); a0.w = fmaf(xv, w0.w, a0.w);
        a1.x = fmaf(xv, w1.x, a1.x); a1.y = fmaf(xv, w1.y, a1.y);
        a1.z = fmaf(xv, w1.z, a1.z); a1.w = fmaf(xv, w1.w, a1.w);
        a2.x = fmaf(xv, w2.x, a2.x); a2.y = fmaf(xv, w2.y, a2.y);
        a2.z = fmaf(xv, w2.z, a2.z); a2.w = fmaf(xv, w2.w, a2.w);
        a3.x = fmaf(xv, w3.x, a3.x); a3.y = fmaf(xv, w3.y, a3.y);
        a3.z = fmaf(xv, w3.z, a3.z); a3.w = fmaf(xv, w3.w, a3.w);
    }
    float4* P = (float4*)((isU ? g_P_u : g_P_i) + ((size_t)r * N + n) * 16);
    P[0] = a0; P[1] = a1; P[2] = a2; P[3] = a3;
}

// ---------------- kernel 1: per-edge ead, wide-load layout (R7) ----------------
__global__ __launch_bounds__(256) void phase1_kernel(
    const float* __restrict__ user_h,     const float* __restrict__ item_h,
    const float* __restrict__ user_hsum,  const float* __restrict__ item_hsum,
    const float* __restrict__ review_feat,
    const float* __restrict__ prototypes, const float* __restrict__ eta,
    const int*   __restrict__ rows,       const int*   __restrict__ cols)
{
    __shared__ float sm[256];
    const int r = blockIdx.y;
    if (threadIdx.x < 256) sm[threadIdx.x] = prototypes[threadIdx.x];
    __syncthreads();

    const int lane = threadIdx.x & 31;
    const int warp = threadIdx.x >> 5;
    const int e = blockIdx.x * 8 + warp;
    if (e >= E_N) return;

    const size_t idx = (size_t)r * E_N + e;
    const int row = rows[idx];
    const int col = cols[idx];
    const unsigned FULL = 0xffffffffu;

    const int dh = lane & 15;
    float hval;
    if (lane < 16) hval = __ldg(user_h + ((size_t)r * U_N + row) * 16 + dh);
    else           hval = __ldg(item_h + ((size_t)r * I_N + col) * 16 + dh);

    const float* uh = user_hsum + ((size_t)r * U_N + row) * 64;
    const float* ih = item_hsum + ((size_t)r * I_N + col) * 64;
    float4 hs;
    if (lane < 16) hs = *(const float4*)(uh + 4 * lane);
    else           hs = *(const float4*)(ih + 4 * (lane - 16));

    const float4* rf4 = (const float4*)(review_feat + idx * 256);
    float4 ra = __ldcs(rf4 + lane * 2);
    float4 rb = __ldcs(rf4 + lane * 2 + 1);

    const float invnu = g_invn_u[(size_t)r * U_N + row];
    const float invni = g_invn_i[(size_t)r * I_N + col];
    const float etav = eta[idx];

    float othv = __shfl_xor_sync(FULL, hval, 16);
    float dot = red16(hval * othv);
    float sim_k = 2.0f * dot * invnu * invni;

    float4 oth;
    oth.x = __shfl_xor_sync(FULL, hs.x, 16);
    oth.y = __shfl_xor_sync(FULL, hs.y, 16);
    oth.z = __shfl_xor_sync(FULL, hs.z, 16);
    oth.w = __shfl_xor_sync(FULL, hs.w, 16);
    float p = hs.x * oth.x + hs.y * oth.y + hs.z * oth.z + hs.w * oth.w;
    p += __shfl_xor_sync(FULL, p, 1);
    p += __shfl_xor_sync(FULL, p, 2);
    float ek = __expf(2.0f * p);
    float Ssim = ek;
    Ssim += __shfl_xor_sync(FULL, Ssim, 4);
    Ssim += __shfl_xor_sync(FULL, Ssim, 8);
    float exp_sim = __expf(sim_k) / Ssim;

    const float4* pr4 = (const float4*)sm;
    float4 pa = pr4[lane * 2];
    float4 pb = pr4[lane * 2 + 1];
    float ad = ra.x * pa.x + ra.y * pa.y + ra.z * pa.z + ra.w * pa.w
             + rb.x * pb.x + rb.y * pb.y + rb.z * pb.z + rb.w * pb.w;
    ad += __shfl_xor_sync(FULL, ad, 1);
    ad += __shfl_xor_sync(FULL, ad, 2);
    ad += __shfl_xor_sync(FULL, ad, 4);
    float eab = __expf(2.0f * ad);
    float Sad = eab;
    Sad += __shfl_xor_sync(FULL, Sad, 8);
    Sad += __shfl_xor_sync(FULL, Sad, 16);
    float e2 = __shfl_sync(FULL, eab, 16);
    float ead = e2 / Sad;

    float g = 1.0f / (1.0f + __expf(-etav));
    ead = g * ead + (1.0f - g) * exp_sim;

    if (lane == 0) {
        g_ead[idx] = ead;
        atomicAdd(&g_norm_u[row], ead);
        atomicAdd(&g_norm_i[col], ead);
    }
}

// ---------------- fused kernel: review projection + weight + scatter ----------------
// Block handles 64 edges. GEMM (FFMA2, smem-staged rf_k) -> smem results ->
// w-weight + P gather + v4 RED scatter. No g_m round-trip.
__global__ __launch_bounds__(256) void proj_scatter_kernel(
    const float* __restrict__ review_feat,
    const float* __restrict__ review_w_fwd, const float* __restrict__ review_w_rev,
    const int* __restrict__ rows, const int* __restrict__ cols,
    float* __restrict__ int_dist_out)
{
    __shared__ float      smWT[32 * 68];        // [o][j], stride 68 (conflict-free LDS.128)
    __shared__ ulonglong2 smrf[32 * 33];        // [pair][j/2], stride 33 units
    __shared__ float      smres[64 * 33];       // [e][o], stride 33 (conflict-free scatter reads)
    const int r = blockIdx.y;
    const int tid = threadIdx.x;

    for (int i = tid; i < 2048; i += 256) {
        int o = i & 31, j = i >> 5;
        float w = (o < 16) ? review_w_fwd[r * 1024 + j * 16 + o]
                           : review_w_rev[r * 1024 + j * 16 + (o - 16)];
        smWT[o * 68 + j] = w;
    }

    const int e0 = blockIdx.x * 64;
    float* smrf_f = (float*)smrf;
    for (int i = tid; i < 1024; i += 256) {
        int e = i >> 4, q = i & 15;
        int eg = e0 + e;
        float4 v = {0,0,0,0};
        if (eg < E_N)
            v = __ldcs((const float4*)(review_feat + ((size_t)r * E_N + eg) * 256 + 128) + q);
        int p = e >> 1, h = e & 1;
        int jf = q * 4;
        int base = (p * 33 + (jf >> 1)) * 4 + h;
        smrf_f[base + 0] = v.x;
        smrf_f[base + 2] = v.y;
        smrf_f[base + 4] = v.z;
        smrf_f[base + 6] = v.w;
    }
    __syncthreads();

    // ---- GEMM: warp owns 4 pairs (8 edges) x 32 outs ----
    {
        const int lane = tid & 31;
        const int warp = tid >> 5;
        const int pbase = warp * 4;
        unsigned long long acc2[4] = {0ull, 0ull, 0ull, 0ull};
        const float4* wt4 = (const float4*)(smWT + lane * 68);
#pragma unroll
        for (int jq = 0; jq < 16; jq++) {
            float4 wv = wt4[jq];
            unsigned long long w0 = dup2(wv.x), w1 = dup2(wv.y);
            unsigned long long w2 = dup2(wv.z), w3 = dup2(wv.w);
#pragma unroll
            for (int pp = 0; pp < 4; pp++) {
                const ulonglong2* rp = smrf + (pbase + pp) * 33 + jq * 2;
                ulonglong2 rva = rp[0];
                ulonglong2 rvb = rp[1];
                acc2[pp] = fma2(rva.x, w0, acc2[pp]);
                acc2[pp] = fma2(rva.y, w1, acc2[pp]);
                acc2[pp] = fma2(rvb.x, w2, acc2[pp]);
                acc2[pp] = fma2(rvb.y, w3, acc2[pp]);
            }
        }
#pragma unroll
        for (int pp = 0; pp < 4; pp++) {
            float lo, hi;
            unpack2(acc2[pp], lo, hi);
            int el = warp * 8 + 2 * pp;          // local edge (even)
            smres[el * 33 + lane] = lo;
            smres[(el + 1) * 33 + lane] = hi;
        }
    }
    __syncthreads();

    // ---- scatter: 8 threads per edge, 2 iterations ----
#pragma unroll
    for (int it = 0; it < 2; it++) {
        int item = tid + it * 256;
        int el = item >> 3;                      // local edge 0..63
        int q  = item & 7;
        int eg = e0 + el;
        if (eg >= E_N) continue;
        const size_t idx = (size_t)r * E_N + eg;
        const int row = rows[idx];
        const int col = cols[idx];
        const float ead = g_ead[idx];
        const float w = ead * rsqrtf(g_norm_u[row] * g_norm_i[col]);
        if (q == 0) int_dist_out[idx] = w;

        float4 p4;
        float* dest;
        const float* res = smres + el * 33;
        float m0, m1, m2, m3;
        if (q < 4) {
            m0 = res[q*4+0]; m1 = res[q*4+1]; m2 = res[q*4+2]; m3 = res[q*4+3];
            p4 = *(const float4*)(g_P_u + ((size_t)r * U_N + row) * 16 + q * 4);
            dest = g_ifeat + col * 16 + q * 4;
        } else {
            const int qq = q - 4;
            m0 = res[16+qq*4+0]; m1 = res[16+qq*4+1]; m2 = res[16+qq*4+2]; m3 = res[16+qq*4+3];
            p4 = *(const float4*)(g_P_i + ((size_t)r * I_N + col) * 16 + qq * 4);
            dest = g_ufeat + row * 16 + qq * 4;
        }
        float4 mv;
        mv.x = (m0 + p4.x) * w;
        mv.y = (m1 + p4.y) * w;
        mv.z = (m2 + p4.z) * w;
        mv.w = (m3 + p4.w) * w;
        red_v4(dest, mv);
    }
}

// ---------------- kernel 3: leaky + FC, weights in registers ----------------
#define NB_U ((U_N + 63) / 64)
#define NB_I ((I_N + 63) / 64)
__global__ __launch_bounds__(256) void fc_kernel(
    const float* __restrict__ ufc_w, const float* __restrict__ ufc_b,
    const float* __restrict__ ifc_w, const float* __restrict__ ifc_b,
    float* __restrict__ out)
{
    __shared__ float smx[64 * 17];
    const int tid = threadIdx.x;
    const bool isU = (blockIdx.x < NB_U);
    const int nb = (isU ? blockIdx.x : (blockIdx.x - NB_U)) * 64;
    const int N = isU ? U_N : I_N;
    const float* feat = isU ? g_ufeat : g_ifeat;
    const float* W = isU ? ufc_w : ifc_w;
    const float* B = isU ? ufc_b : ifc_b;
    float* outp = out + (isU ? 0 : (size_t)U_N * 64);

    for (int i = tid; i < 1024; i += 256) {
        int n = i >> 4, j = i & 15;
        int ng = nb + n;
        float x = (ng < N) ? feat[ng * 16 + j] : 0.f;
        x = (x >= 0.f) ? x : 0.1f * x;
        smx[n * 17 + j] = x;
    }
    __syncthreads();

    const int o = tid & 63;
    const int g = tid >> 6;
    float wr[16];
#pragma unroll
    for (int j = 0; j < 16; j++) wr[j] = W[j * 64 + o];
    const float b = B[o];

#pragma unroll
    for (int i = 0; i < 16; i++) {
        int n = g + i * 4;
        int ng = nb + n;
        if (ng < N) {
            float acc = b;
#pragma unroll
            for (int j = 0; j < 16; j++) acc = fmaf(smx[n * 17 + j], wr[j], acc);
            outp[(size_t)ng * 64 + o] = acc;
        }
    }
}

// ---------------- launch ----------------
extern "C" void kernel_launch(void* const* d_in, const int* in_sizes, int n_in,
                              void* d_out, int out_size)
{
    const float* user_h       = (const float*)d_in[0];
    const float* item_h       = (const float*)d_in[1];
    const float* user_hsum    = (const float*)d_in[2];
    const float* item_hsum    = (const float*)d_in[3];
    const float* review_feat  = (const float*)d_in[4];
    const float* prototypes   = (const float*)d_in[5];
    const float* eta          = (const float*)d_in[6];
    const float* node_w_fwd   = (const float*)d_in[7];
    const float* node_w_rev   = (const float*)d_in[8];
    const float* review_w_fwd = (const float*)d_in[9];
    const float* review_w_rev = (const float*)d_in[10];
    const float* ufc_w        = (const float*)d_in[11];
    const float* ufc_b        = (const float*)d_in[12];
    const float* ifc_w        = (const float*)d_in[13];
    const float* ifc_b        = (const float*)d_in[14];
    const int*   rows         = (const int*)d_in[15];
    const int*   cols         = (const int*)d_in[16];
    float* out = (float*)d_out;

    dim3 pgrid((U_N + 255) / 256, R_N, 2);
    precompute_kernel<<<pgrid, 256>>>(user_h, item_h, node_w_fwd, node_w_rev);

    dim3 egrid(E_N / 8, R_N);
    phase1_kernel<<<egrid, 256>>>(user_h, item_h, user_hsum, item_hsum,
                                  review_feat, prototypes, eta, rows, cols);

    dim3 bgrid((E_N + 63) / 64, R_N);
    proj_scatter_kernel<<<bgrid, 256>>>(review_feat, review_w_fwd, review_w_rev,
                                        rows, cols,
                                        out + (size_t)(U_N + I_N) * OUT_N);

    fc_kernel<<<NB_U + NB_I, 256>>>(ufc_w, ufc_b, ifc_w, ifc_b, out);
}